// round 1
// baseline (speedup 1.0000x reference)
#include <cuda_runtime.h>
#include <cstdint>

#define NN   50000
#define TT   128
#define INF  6
#define HH   32
#define NE   2000
#define NI   150000
#define RRF  16

typedef unsigned long long u64;

// ---------------- scratch (device globals, no allocation) ----------------
__device__ float g_A  [NN * HH];   // activations between stages
__device__ float g_XW [NN * HH];   // x @ W^T
__device__ float g_AGG[NN * HH];   // node aggregation
__device__ float g_EF [NE * HH];   // edge features
__device__ float g_degB[NE];       // edge degree -> inverted in place
__device__ float g_degD[NN];       // node degree -> inverted in place

// ---------------- helpers ----------------
__device__ __forceinline__ u64 ffma2(u64 a, u64 b, u64 c) {
    u64 d;
    asm("fma.rn.f32x2 %0, %1, %2, %3;" : "=l"(d) : "l"(a), "l"(b), "l"(c));
    return d;
}
__device__ __forceinline__ u64 pk2(float lo, float hi) {
    u64 r;
    asm("mov.b64 %0, {%1, %2};" : "=l"(r) : "f"(lo), "f"(hi));
    return r;
}
__device__ __forceinline__ float2 up2(u64 v) {
    float2 f;
    asm("mov.b64 {%0, %1}, %2;" : "=f"(f.x), "=f"(f.y) : "l"(v));
    return f;
}
// sigmoid / tanh via EX2 + RCP (MUFU), rel err ~1e-7
__device__ __forceinline__ float sigm(float x) {
    return __fdividef(1.f, 1.f + __expf(-x));
}
__device__ __forceinline__ float tanh_fast(float x) {
    return __fdividef(2.f, 1.f + __expf(-2.f * x)) - 1.f;
}

// ---------------- GRU kernel ----------------
// One thread = one node. h[32] in registers, weights packed as f32x2 pairs
// (adjacent gate outputs) in shared memory, broadcast LDS.
struct __align__(16) SmemGRU {
    u64 wr[32 * 16], wz[32 * 16], wn[32 * 16];  // W_hh pairs, [k][jp]
    u64 uir[6 * 16], uiz[6 * 16], uin[6 * 16];  // W_ih pairs, [f][jp]
    u64 br[16], bz[16], bhn[16], bin[16];       // biases
};

__global__ void __launch_bounds__(128) gru_kernel(
    const float* __restrict__ x,
    const float* __restrict__ W_ih, const float* __restrict__ W_hh,
    const float* __restrict__ b_ih, const float* __restrict__ b_hh)
{
    __shared__ SmemGRU sm;
    const int tid = threadIdx.x;

    for (int idx = tid; idx < 512; idx += 128) {
        int k = idx >> 4, jp = idx & 15;
        sm.wr[idx] = pk2(W_hh[(     2 * jp) * HH + k], W_hh[(     2 * jp + 1) * HH + k]);
        sm.wz[idx] = pk2(W_hh[(32 + 2 * jp) * HH + k], W_hh[(32 + 2 * jp + 1) * HH + k]);
        sm.wn[idx] = pk2(W_hh[(64 + 2 * jp) * HH + k], W_hh[(64 + 2 * jp + 1) * HH + k]);
    }
    for (int idx = tid; idx < 96; idx += 128) {
        int f = idx >> 4, jp = idx & 15;
        sm.uir[idx] = pk2(W_ih[(     2 * jp) * INF + f], W_ih[(     2 * jp + 1) * INF + f]);
        sm.uiz[idx] = pk2(W_ih[(32 + 2 * jp) * INF + f], W_ih[(32 + 2 * jp + 1) * INF + f]);
        sm.uin[idx] = pk2(W_ih[(64 + 2 * jp) * INF + f], W_ih[(64 + 2 * jp + 1) * INF + f]);
    }
    if (tid < 16) {
        int jp = tid;
        sm.br [jp] = pk2(b_ih[2 * jp] + b_hh[2 * jp],
                         b_ih[2 * jp + 1] + b_hh[2 * jp + 1]);
        sm.bz [jp] = pk2(b_ih[32 + 2 * jp] + b_hh[32 + 2 * jp],
                         b_ih[32 + 2 * jp + 1] + b_hh[32 + 2 * jp + 1]);
        sm.bhn[jp] = pk2(b_hh[64 + 2 * jp], b_hh[64 + 2 * jp + 1]);
        sm.bin[jp] = pk2(b_ih[64 + 2 * jp], b_ih[64 + 2 * jp + 1]);
    }
    __syncthreads();

    const int node = blockIdx.x * 128 + tid;
    const int nc = node < NN ? node : NN - 1;
    const float* xp = x + (size_t)nc * (TT * INF);

    float h[32];
#pragma unroll
    for (int i = 0; i < 32; i++) h[i] = 0.f;

    float xv[6], xn[6];
#pragma unroll
    for (int f = 0; f < 6; f++) xv[f] = xp[f];

    for (int t = 0; t < TT; t++) {
        if (t < TT - 1) {
            const float* p = xp + (t + 1) * INF;
#pragma unroll
            for (int f = 0; f < 6; f++) xn[f] = p[f];
        }

        // ---- r and z gates: acc = b_ih+b_hh + W_ih x + W_hh h ----
        u64 ar[16], az[16];
#pragma unroll
        for (int jp = 0; jp < 16; jp++) { ar[jp] = sm.br[jp]; az[jp] = sm.bz[jp]; }

#pragma unroll
        for (int f = 0; f < 6; f++) {
            u64 xd = pk2(xv[f], xv[f]);
            const ulonglong2* pr = reinterpret_cast<const ulonglong2*>(&sm.uir[f * 16]);
            const ulonglong2* pz = reinterpret_cast<const ulonglong2*>(&sm.uiz[f * 16]);
#pragma unroll
            for (int j2 = 0; j2 < 8; j2++) {
                ulonglong2 a = pr[j2];
                ar[2 * j2]     = ffma2(a.x, xd, ar[2 * j2]);
                ar[2 * j2 + 1] = ffma2(a.y, xd, ar[2 * j2 + 1]);
                ulonglong2 b = pz[j2];
                az[2 * j2]     = ffma2(b.x, xd, az[2 * j2]);
                az[2 * j2 + 1] = ffma2(b.y, xd, az[2 * j2 + 1]);
            }
        }
#pragma unroll 8
        for (int k = 0; k < 32; k++) {
            u64 hd = pk2(h[k], h[k]);
            const ulonglong2* pr = reinterpret_cast<const ulonglong2*>(&sm.wr[k * 16]);
            const ulonglong2* pz = reinterpret_cast<const ulonglong2*>(&sm.wz[k * 16]);
#pragma unroll
            for (int j2 = 0; j2 < 8; j2++) {
                ulonglong2 a = pr[j2];
                ar[2 * j2]     = ffma2(a.x, hd, ar[2 * j2]);
                ar[2 * j2 + 1] = ffma2(a.y, hd, ar[2 * j2 + 1]);
                ulonglong2 b = pz[j2];
                az[2 * j2]     = ffma2(b.x, hd, az[2 * j2]);
                az[2 * j2 + 1] = ffma2(b.y, hd, az[2 * j2 + 1]);
            }
        }

        u64 r2[16], z2[16];
#pragma unroll
        for (int jp = 0; jp < 16; jp++) {
            float2 a = up2(ar[jp]);
            r2[jp] = pk2(sigm(a.x), sigm(a.y));
            float2 b = up2(az[jp]);
            z2[jp] = pk2(sigm(b.x), sigm(b.y));
        }

        // ---- n gate: n = tanh( (b_ih_n + W_ih_n x) + r * (b_hh_n + W_hh_n h) ) ----
        u64 an[16];
#pragma unroll
        for (int jp = 0; jp < 16; jp++) an[jp] = sm.bhn[jp];
#pragma unroll 8
        for (int k = 0; k < 32; k++) {
            u64 hd = pk2(h[k], h[k]);
            const ulonglong2* pn = reinterpret_cast<const ulonglong2*>(&sm.wn[k * 16]);
#pragma unroll
            for (int j2 = 0; j2 < 8; j2++) {
                ulonglong2 a = pn[j2];
                an[2 * j2]     = ffma2(a.x, hd, an[2 * j2]);
                an[2 * j2 + 1] = ffma2(a.y, hd, an[2 * j2 + 1]);
            }
        }
#pragma unroll
        for (int jp = 0; jp < 16; jp++) an[jp] = ffma2(r2[jp], an[jp], sm.bin[jp]);
#pragma unroll
        for (int f = 0; f < 6; f++) {
            u64 xd = pk2(xv[f], xv[f]);
#pragma unroll
            for (int jp = 0; jp < 16; jp++) an[jp] = ffma2(sm.uin[f * 16 + jp], xd, an[jp]);
        }

        // ---- h' = n + z*(h - n) ----
#pragma unroll
        for (int jp = 0; jp < 16; jp++) {
            float2 v  = up2(an[jp]);
            float2 zz = up2(z2[jp]);
            float n0 = tanh_fast(v.x), n1 = tanh_fast(v.y);
            h[2 * jp]     = n0 + zz.x * (h[2 * jp]     - n0);
            h[2 * jp + 1] = n1 + zz.y * (h[2 * jp + 1] - n1);
        }
#pragma unroll
        for (int f = 0; f < 6; f++) xv[f] = xn[f];
    }

    if (node < NN) {
#pragma unroll
        for (int c = 0; c < 32; c++) {
            float v = h[c];
            g_A[(size_t)node * 32 + c] = v > 0.f ? v : 0.01f * v;  // leaky 0.01
        }
    }
}

// ---------------- hypergraph kernels ----------------
__global__ void zero_deg_kernel() {
    int i = blockIdx.x * blockDim.x + threadIdx.x;
    if (i < NE) g_degB[i] = 0.f;
    if (i < NN) g_degD[i] = 0.f;
}
__global__ void count_deg_kernel(const int* __restrict__ nidx, const int* __restrict__ eidx) {
    int i = blockIdx.x * blockDim.x + threadIdx.x;
    if (i < NI) {
        atomicAdd(&g_degB[eidx[i]], 1.f);
        atomicAdd(&g_degD[nidx[i]], 1.f);
    }
}
__global__ void invert_deg_kernel() {
    int i = blockIdx.x * blockDim.x + threadIdx.x;
    if (i < NE) { float v = g_degB[i]; g_degB[i] = v > 0.f ? 1.f / v : 0.f; }
    if (i < NN) { float v = g_degD[i]; g_degD[i] = v > 0.f ? 1.f / v : 0.f; }
}
__global__ void zero_ef_kernel() {
    int i = blockIdx.x * blockDim.x + threadIdx.x;
    if (i < NE * HH) g_EF[i] = 0.f;
}
__global__ void zero_agg_kernel() {
    int i = blockIdx.x * blockDim.x + threadIdx.x;
    if (i < NN * HH) g_AGG[i] = 0.f;
}
__global__ void scatter_edge_kernel(const int* __restrict__ nidx, const int* __restrict__ eidx) {
    int idx = blockIdx.x * blockDim.x + threadIdx.x;
    if (idx < NI * HH) {
        int i = idx >> 5, c = idx & 31;
        atomicAdd(&g_EF[eidx[i] * HH + c], g_XW[(size_t)nidx[i] * HH + c]);
    }
}
__global__ void scatter_node_kernel(const int* __restrict__ nidx, const int* __restrict__ eidx) {
    int idx = blockIdx.x * blockDim.x + threadIdx.x;
    if (idx < NI * HH) {
        int i = idx >> 5, c = idx & 31;
        int e = eidx[i];
        atomicAdd(&g_AGG[(size_t)nidx[i] * HH + c], g_EF[e * HH + c] * g_degB[e]);
    }
}
__global__ void finalize_kernel(const float* __restrict__ bias) {
    int idx = blockIdx.x * blockDim.x + threadIdx.x;
    if (idx < NN * HH) {
        int n = idx >> 5, c = idx & 31;
        float v = g_AGG[idx] * g_degD[n] + bias[c];
        g_A[idx] = v > 0.f ? v : 0.2f * v;  // leaky 0.2
    }
}
// out[n,j] = act( g_A[n,:] @ W[j,:] + b[j] ); writes g_XW unless extout given.
__global__ void dense_kernel(const float* __restrict__ W, const float* __restrict__ bias,
                             float* __restrict__ extout,
                             int nout, int hasBias, int hasAct, float slope) {
    __shared__ float sW[32 * 32];
    for (int i = threadIdx.x; i < nout * 32; i += blockDim.x) sW[i] = W[i];
    __syncthreads();
    int n = blockIdx.x * blockDim.x + threadIdx.x;
    if (n >= NN) return;
    float xin[32];
#pragma unroll
    for (int k = 0; k < 32; k++) xin[k] = g_A[(size_t)n * 32 + k];
    float* o = extout ? extout : g_XW;
    for (int j = 0; j < nout; j++) {
        float acc = hasBias ? bias[j] : 0.f;
#pragma unroll
        for (int k = 0; k < 32; k++) acc = fmaf(xin[k], sW[j * 32 + k], acc);
        if (hasAct) acc = acc > 0.f ? acc : slope * acc;
        o[(size_t)n * nout + j] = acc;
    }
}

// ---------------- launch ----------------
extern "C" void kernel_launch(void* const* d_in, const int* in_sizes, int n_in,
                              void* d_out, int out_size) {
    const float* price = (const float*)d_in[0];
    // d_in[1] = concept (unused on this path)
    const float* W_ih = (const float*)d_in[2];
    const float* W_hh = (const float*)d_in[3];
    const float* b_ih = (const float*)d_in[4];
    const float* b_hh = (const float*)d_in[5];
    const float* W1   = (const float*)d_in[6];
    const float* b1   = (const float*)d_in[7];
    const float* W2   = (const float*)d_in[8];
    const float* b2   = (const float*)d_in[9];
    const float* Wl   = (const float*)d_in[10];
    const float* bl   = (const float*)d_in[11];
    const int*   nidx = (const int*)d_in[12];
    const int*   eidx = (const int*)d_in[13];
    float* out = (float*)d_out;

    const int B256 = 256;
    // degrees (index-only, cheap)
    zero_deg_kernel<<<(NN + B256 - 1) / B256, B256>>>();
    count_deg_kernel<<<(NI + B256 - 1) / B256, B256>>>(nidx, eidx);
    invert_deg_kernel<<<(NN + B256 - 1) / B256, B256>>>();

    // GRU -> g_A (leaky 0.01 applied)
    gru_kernel<<<(NN + 127) / 128, 128>>>(price, W_ih, W_hh, b_ih, b_hh);

    // conv1
    dense_kernel<<<(NN + 127) / 128, 128>>>(W1, nullptr, nullptr, 32, 0, 0, 0.f);
    zero_ef_kernel<<<(NE * HH + B256 - 1) / B256, B256>>>();
    scatter_edge_kernel<<<(NI * HH + B256 - 1) / B256, B256>>>(nidx, eidx);
    zero_agg_kernel<<<(NN * HH + B256 - 1) / B256, B256>>>();
    scatter_node_kernel<<<(NI * HH + B256 - 1) / B256, B256>>>(nidx, eidx);
    finalize_kernel<<<(NN * HH + B256 - 1) / B256, B256>>>(b1);

    // conv2
    dense_kernel<<<(NN + 127) / 128, 128>>>(W2, nullptr, nullptr, 32, 0, 0, 0.f);
    zero_ef_kernel<<<(NE * HH + B256 - 1) / B256, B256>>>();
    scatter_edge_kernel<<<(NI * HH + B256 - 1) / B256, B256>>>(nidx, eidx);
    zero_agg_kernel<<<(NN * HH + B256 - 1) / B256, B256>>>();
    scatter_node_kernel<<<(NI * HH + B256 - 1) / B256, B256>>>(nidx, eidx);
    finalize_kernel<<<(NN * HH + B256 - 1) / B256, B256>>>(b2);

    // final linear + leaky 0.01 -> d_out
    dense_kernel<<<(NN + 127) / 128, 128>>>(Wl, bl, out, RRF, 1, 1, 0.01f);
}

// round 2
// speedup vs baseline: 1.4435x; 1.4435x over previous
#include <cuda_runtime.h>
#include <cstdint>

#define NN   50000
#define TT   128
#define INF  6
#define HH   32
#define NE   2000
#define NI   150000
#define RRF  16

typedef unsigned long long u64;

// ---------------- scratch (device globals, no allocation) ----------------
__device__ float g_A  [NN * HH];   // activations between stages
__device__ float g_XW [NN * HH];   // x @ W^T
__device__ float g_AGG[NN * HH];   // node aggregation
__device__ float g_EF [NE * HH];   // edge features
__device__ float g_degB[NE];       // edge degree -> inverted in place
__device__ float g_degD[NN];       // node degree -> inverted in place
__device__ float g_XT [(size_t)TT * INF * NN];  // transposed price: [t][f][node]

// ---------------- helpers ----------------
__device__ __forceinline__ u64 ffma2(u64 a, u64 b, u64 c) {
    u64 d;
    asm("fma.rn.f32x2 %0, %1, %2, %3;" : "=l"(d) : "l"(a), "l"(b), "l"(c));
    return d;
}
__device__ __forceinline__ u64 pk2(float lo, float hi) {
    u64 r;
    asm("mov.b64 %0, {%1, %2};" : "=l"(r) : "f"(lo), "f"(hi));
    return r;
}
__device__ __forceinline__ float2 up2(u64 v) {
    float2 f;
    asm("mov.b64 {%0, %1}, %2;" : "=f"(f.x), "=f"(f.y) : "l"(v));
    return f;
}
__device__ __forceinline__ float sigm(float x) {
    return __fdividef(1.f, 1.f + __expf(-x));
}
__device__ __forceinline__ float tanh_fast(float x) {
    return __fdividef(2.f, 1.f + __expf(-2.f * x)) - 1.f;
}

// ---------------- transpose price [n][t][f] -> [t][f][n] ----------------
__global__ void __launch_bounds__(256) transpose_kernel(const float* __restrict__ x) {
    __shared__ float s[8 * TT * INF];   // 8 nodes, full T: 24 KB
    const int n0 = blockIdx.x * 8;
    const float* src = x + (size_t)n0 * TT * INF;
    for (int i = threadIdx.x; i < 8 * TT * INF; i += 256) s[i] = src[i];
    __syncthreads();
    for (int i = threadIdx.x; i < 8 * TT * INF; i += 256) {
        int n = i & 7;
        int tf = i >> 3;
        int f = tf % INF;
        int t = tf / INF;
        g_XT[((size_t)t * INF + f) * NN + n0 + n] = s[(n * TT + t) * INF + f];
    }
}

// ---------------- GRU kernel ----------------
// One thread = one node. h[32] in registers; weights packed as f32x2 pairs in
// shared (uniform broadcast LDS). Gate passes sequential to cap live regs.
struct __align__(16) SmemGRU {
    u64 wn[32 * 16], wr[32 * 16], wz[32 * 16];  // W_hh pairs [k][jp]
    u64 uin[6 * 16], uir[6 * 16], uiz[6 * 16];  // W_ih pairs [f][jp]
    u64 bhn[16], br[16], bz[16], bin[16];
};

__global__ void __launch_bounds__(64, 8) gru_kernel(
    const float* __restrict__ W_ih, const float* __restrict__ W_hh,
    const float* __restrict__ b_ih, const float* __restrict__ b_hh)
{
    __shared__ SmemGRU sm;
    const int tid = threadIdx.x;

    for (int idx = tid; idx < 512; idx += 64) {
        int k = idx >> 4, jp = idx & 15;
        sm.wn[idx] = pk2(W_hh[(64 + 2 * jp) * HH + k], W_hh[(64 + 2 * jp + 1) * HH + k]);
        sm.wr[idx] = pk2(W_hh[(     2 * jp) * HH + k], W_hh[(     2 * jp + 1) * HH + k]);
        sm.wz[idx] = pk2(W_hh[(32 + 2 * jp) * HH + k], W_hh[(32 + 2 * jp + 1) * HH + k]);
    }
    for (int idx = tid; idx < 96; idx += 64) {
        int f = idx >> 4, jp = idx & 15;
        sm.uin[idx] = pk2(W_ih[(64 + 2 * jp) * INF + f], W_ih[(64 + 2 * jp + 1) * INF + f]);
        sm.uir[idx] = pk2(W_ih[(     2 * jp) * INF + f], W_ih[(     2 * jp + 1) * INF + f]);
        sm.uiz[idx] = pk2(W_ih[(32 + 2 * jp) * INF + f], W_ih[(32 + 2 * jp + 1) * INF + f]);
    }
    if (tid < 16) {
        int jp = tid;
        sm.br [jp] = pk2(b_ih[2 * jp] + b_hh[2 * jp],
                         b_ih[2 * jp + 1] + b_hh[2 * jp + 1]);
        sm.bz [jp] = pk2(b_ih[32 + 2 * jp] + b_hh[32 + 2 * jp],
                         b_ih[32 + 2 * jp + 1] + b_hh[32 + 2 * jp + 1]);
        sm.bhn[jp] = pk2(b_hh[64 + 2 * jp], b_hh[64 + 2 * jp + 1]);
        sm.bin[jp] = pk2(b_ih[64 + 2 * jp], b_ih[64 + 2 * jp + 1]);
    }
    __syncthreads();

    const int node = blockIdx.x * 64 + tid;
    const int nc = node < NN ? node : NN - 1;

    float h[32];
#pragma unroll
    for (int i = 0; i < 32; i++) h[i] = 0.f;

    float xv[6], xn[6];
#pragma unroll
    for (int f = 0; f < 6; f++) xv[f] = g_XT[(size_t)f * NN + nc];

    u64 accN[16], accR[16];

    for (int t = 0; t < TT; t++) {
        if (t < TT - 1) {
#pragma unroll
            for (int f = 0; f < 6; f++)
                xn[f] = g_XT[((size_t)(t + 1) * INF + f) * NN + nc];
        }

        // ---- pass 1: accN = b_hh_n + W_hh_n h (uses OLD h) ----
#pragma unroll
        for (int jp = 0; jp < 16; jp++) accN[jp] = sm.bhn[jp];
#pragma unroll 8
        for (int k = 0; k < 32; k++) {
            u64 hd = pk2(h[k], h[k]);
            const ulonglong2* p = reinterpret_cast<const ulonglong2*>(&sm.wn[k * 16]);
#pragma unroll
            for (int j2 = 0; j2 < 8; j2++) {
                ulonglong2 a = p[j2];
                accN[2 * j2]     = ffma2(a.x, hd, accN[2 * j2]);
                accN[2 * j2 + 1] = ffma2(a.y, hd, accN[2 * j2 + 1]);
            }
        }

        // ---- pass 2: r = sigm(b + W_ih_r x + W_hh_r h) ----
#pragma unroll
        for (int jp = 0; jp < 16; jp++) accR[jp] = sm.br[jp];
#pragma unroll 8
        for (int k = 0; k < 32; k++) {
            u64 hd = pk2(h[k], h[k]);
            const ulonglong2* p = reinterpret_cast<const ulonglong2*>(&sm.wr[k * 16]);
#pragma unroll
            for (int j2 = 0; j2 < 8; j2++) {
                ulonglong2 a = p[j2];
                accR[2 * j2]     = ffma2(a.x, hd, accR[2 * j2]);
                accR[2 * j2 + 1] = ffma2(a.y, hd, accR[2 * j2 + 1]);
            }
        }
#pragma unroll
        for (int f = 0; f < 6; f++) {
            u64 xd = pk2(xv[f], xv[f]);
#pragma unroll
            for (int jp = 0; jp < 16; jp++)
                accR[jp] = ffma2(sm.uir[f * 16 + jp], xd, accR[jp]);
        }
#pragma unroll
        for (int jp = 0; jp < 16; jp++) {
            float2 a = up2(accR[jp]);
            accR[jp] = pk2(sigm(a.x), sigm(a.y));
        }

        // ---- n = tanh( b_ih_n + W_ih_n x + r * accN ) ----
#pragma unroll
        for (int jp = 0; jp < 16; jp++) accN[jp] = ffma2(accR[jp], accN[jp], sm.bin[jp]);
#pragma unroll
        for (int f = 0; f < 6; f++) {
            u64 xd = pk2(xv[f], xv[f]);
#pragma unroll
            for (int jp = 0; jp < 16; jp++)
                accN[jp] = ffma2(sm.uin[f * 16 + jp], xd, accN[jp]);
        }
#pragma unroll
        for (int jp = 0; jp < 16; jp++) {
            float2 v = up2(accN[jp]);
            accN[jp] = pk2(tanh_fast(v.x), tanh_fast(v.y));
        }

        // ---- pass 3: z = sigm(b + W_ih_z x + W_hh_z h) (OLD h) ----
#pragma unroll
        for (int jp = 0; jp < 16; jp++) accR[jp] = sm.bz[jp];
#pragma unroll 8
        for (int k = 0; k < 32; k++) {
            u64 hd = pk2(h[k], h[k]);
            const ulonglong2* p = reinterpret_cast<const ulonglong2*>(&sm.wz[k * 16]);
#pragma unroll
            for (int j2 = 0; j2 < 8; j2++) {
                ulonglong2 a = p[j2];
                accR[2 * j2]     = ffma2(a.x, hd, accR[2 * j2]);
                accR[2 * j2 + 1] = ffma2(a.y, hd, accR[2 * j2 + 1]);
            }
        }
#pragma unroll
        for (int f = 0; f < 6; f++) {
            u64 xd = pk2(xv[f], xv[f]);
#pragma unroll
            for (int jp = 0; jp < 16; jp++)
                accR[jp] = ffma2(sm.uiz[f * 16 + jp], xd, accR[jp]);
        }

        // ---- h' = n + z*(h - n) ----
#pragma unroll
        for (int jp = 0; jp < 16; jp++) {
            float2 za = up2(accR[jp]);
            float z0 = sigm(za.x), z1 = sigm(za.y);
            float2 nn = up2(accN[jp]);
            h[2 * jp]     = nn.x + z0 * (h[2 * jp]     - nn.x);
            h[2 * jp + 1] = nn.y + z1 * (h[2 * jp + 1] - nn.y);
        }
#pragma unroll
        for (int f = 0; f < 6; f++) xv[f] = xn[f];
    }

    if (node < NN) {
#pragma unroll
        for (int c = 0; c < 32; c++) {
            float v = h[c];
            g_A[(size_t)node * 32 + c] = v > 0.f ? v : 0.01f * v;  // leaky 0.01
        }
    }
}

// ---------------- hypergraph kernels ----------------
__global__ void zero_deg_kernel() {
    int i = blockIdx.x * blockDim.x + threadIdx.x;
    if (i < NE) g_degB[i] = 0.f;
    if (i < NN) g_degD[i] = 0.f;
}
__global__ void count_deg_kernel(const int* __restrict__ nidx, const int* __restrict__ eidx) {
    int i = blockIdx.x * blockDim.x + threadIdx.x;
    if (i < NI) {
        atomicAdd(&g_degB[eidx[i]], 1.f);
        atomicAdd(&g_degD[nidx[i]], 1.f);
    }
}
__global__ void invert_deg_kernel() {
    int i = blockIdx.x * blockDim.x + threadIdx.x;
    if (i < NE) { float v = g_degB[i]; g_degB[i] = v > 0.f ? 1.f / v : 0.f; }
    if (i < NN) { float v = g_degD[i]; g_degD[i] = v > 0.f ? 1.f / v : 0.f; }
}
__global__ void zero_ef_kernel() {
    int i = blockIdx.x * blockDim.x + threadIdx.x;
    if (i < NE * HH) g_EF[i] = 0.f;
}
__global__ void zero_agg_kernel() {
    int i = blockIdx.x * blockDim.x + threadIdx.x;
    if (i < NN * HH) g_AGG[i] = 0.f;
}
__global__ void scatter_edge_kernel(const int* __restrict__ nidx, const int* __restrict__ eidx) {
    int idx = blockIdx.x * blockDim.x + threadIdx.x;
    if (idx < NI * HH) {
        int i = idx >> 5, c = idx & 31;
        atomicAdd(&g_EF[eidx[i] * HH + c], g_XW[(size_t)nidx[i] * HH + c]);
    }
}
__global__ void scatter_node_kernel(const int* __restrict__ nidx, const int* __restrict__ eidx) {
    int idx = blockIdx.x * blockDim.x + threadIdx.x;
    if (idx < NI * HH) {
        int i = idx >> 5, c = idx & 31;
        int e = eidx[i];
        atomicAdd(&g_AGG[(size_t)nidx[i] * HH + c], g_EF[e * HH + c] * g_degB[e]);
    }
}
__global__ void finalize_kernel(const float* __restrict__ bias) {
    int idx = blockIdx.x * blockDim.x + threadIdx.x;
    if (idx < NN * HH) {
        int n = idx >> 5, c = idx & 31;
        float v = g_AGG[idx] * g_degD[n] + bias[c];
        g_A[idx] = v > 0.f ? v : 0.2f * v;  // leaky 0.2
    }
}
__global__ void dense_kernel(const float* __restrict__ W, const float* __restrict__ bias,
                             float* __restrict__ extout,
                             int nout, int hasBias, int hasAct, float slope) {
    __shared__ float sW[32 * 32];
    for (int i = threadIdx.x; i < nout * 32; i += blockDim.x) sW[i] = W[i];
    __syncthreads();
    int n = blockIdx.x * blockDim.x + threadIdx.x;
    if (n >= NN) return;
    float xin[32];
#pragma unroll
    for (int k = 0; k < 32; k++) xin[k] = g_A[(size_t)n * 32 + k];
    float* o = extout ? extout : g_XW;
    for (int j = 0; j < nout; j++) {
        float acc = hasBias ? bias[j] : 0.f;
#pragma unroll
        for (int k = 0; k < 32; k++) acc = fmaf(xin[k], sW[j * 32 + k], acc);
        if (hasAct) acc = acc > 0.f ? acc : slope * acc;
        o[(size_t)n * nout + j] = acc;
    }
}

// ---------------- launch ----------------
extern "C" void kernel_launch(void* const* d_in, const int* in_sizes, int n_in,
                              void* d_out, int out_size) {
    const float* price = (const float*)d_in[0];
    const float* W_ih = (const float*)d_in[2];
    const float* W_hh = (const float*)d_in[3];
    const float* b_ih = (const float*)d_in[4];
    const float* b_hh = (const float*)d_in[5];
    const float* W1   = (const float*)d_in[6];
    const float* b1   = (const float*)d_in[7];
    const float* W2   = (const float*)d_in[8];
    const float* b2   = (const float*)d_in[9];
    const float* Wl   = (const float*)d_in[10];
    const float* bl   = (const float*)d_in[11];
    const int*   nidx = (const int*)d_in[12];
    const int*   eidx = (const int*)d_in[13];
    float* out = (float*)d_out;

    const int B256 = 256;
    zero_deg_kernel<<<(NN + B256 - 1) / B256, B256>>>();
    count_deg_kernel<<<(NI + B256 - 1) / B256, B256>>>(nidx, eidx);
    invert_deg_kernel<<<(NN + B256 - 1) / B256, B256>>>();

    transpose_kernel<<<NN / 8, 256>>>(price);
    gru_kernel<<<(NN + 63) / 64, 64>>>(W_ih, W_hh, b_ih, b_hh);

    // conv1
    dense_kernel<<<(NN + 127) / 128, 128>>>(W1, nullptr, nullptr, 32, 0, 0, 0.f);
    zero_ef_kernel<<<(NE * HH + B256 - 1) / B256, B256>>>();
    scatter_edge_kernel<<<(NI * HH + B256 - 1) / B256, B256>>>(nidx, eidx);
    zero_agg_kernel<<<(NN * HH + B256 - 1) / B256, B256>>>();
    scatter_node_kernel<<<(NI * HH + B256 - 1) / B256, B256>>>(nidx, eidx);
    finalize_kernel<<<(NN * HH + B256 - 1) / B256, B256>>>(b1);

    // conv2
    dense_kernel<<<(NN + 127) / 128, 128>>>(W2, nullptr, nullptr, 32, 0, 0, 0.f);
    zero_ef_kernel<<<(NE * HH + B256 - 1) / B256, B256>>>();
    scatter_edge_kernel<<<(NI * HH + B256 - 1) / B256, B256>>>(nidx, eidx);
    zero_agg_kernel<<<(NN * HH + B256 - 1) / B256, B256>>>();
    scatter_node_kernel<<<(NI * HH + B256 - 1) / B256, B256>>>(nidx, eidx);
    finalize_kernel<<<(NN * HH + B256 - 1) / B256, B256>>>(b2);

    dense_kernel<<<(NN + 127) / 128, 128>>>(Wl, bl, out, RRF, 1, 1, 0.01f);
}